// round 1
// baseline (speedup 1.0000x reference)
#include <cuda_runtime.h>
#include <math.h>

#define BATCH 8
#define NPTS  16384
#define M_KV  64
#define P     16
#define PP    20   // padded point pitch (floats), multiple of 4 for float4

// ---------------- scratch (static device globals: allowed) ----------------
__device__ float g_qpW2T[65536];     // [h][d] = qp_W2[d][h]
__device__ float g_WqT  [65536];     // [d][e] = in_W[e][d]
__device__ float g_WkT  [65536];     // [d][e] = in_W[256+e][d]
__device__ float g_WvT  [65536];     // [d][e] = in_W[512+e][d]
__device__ float g_outWT[65536];     // [d][e] = out_W[e][d]
__device__ float g_net2T[5*65536];   // [i][d][h] = net2_W[i][h][d]
__device__ float g_net1T[4*65536];   // [i][h][g] = net1_W[i][g][h]
__device__ float g_Kt   [BATCH*8*32*M_KV];   // [b][head][k][m]
__device__ float g_V    [BATCH*M_KV*256];    // [b][m][e]

// ---------------- prep: transpose all 256x256 weights ----------------
__global__ void prep_transpose(const float* __restrict__ qp_W2,
                               const float* __restrict__ in_W,
                               const float* __restrict__ out_W,
                               const float* __restrict__ net2_W,
                               const float* __restrict__ net1_W) {
    int mid = blockIdx.y;
    int i = blockIdx.x;      // dst row
    int j = threadIdx.x;     // dst col
    const float* src;
    float* dst;
    switch (mid) {
        case 0: src = qp_W2;            dst = g_qpW2T; break;
        case 1: src = in_W;             dst = g_WqT;   break;
        case 2: src = in_W + 65536;     dst = g_WkT;   break;
        case 3: src = in_W + 131072;    dst = g_WvT;   break;
        case 4: src = out_W;            dst = g_outWT; break;
        default:
            if (mid < 10) { src = net2_W + (mid-5)*65536;  dst = g_net2T + (mid-5)*65536; }
            else          { src = net1_W + (mid-10)*65536; dst = g_net1T + (mid-10)*65536; }
    }
    dst[i*256 + j] = src[j*256 + i];
}

// ---------------- prep: LayerNorm(z) -> K, V ----------------
__global__ void kv_kernel(const float* __restrict__ z_multi,
                          const float* __restrict__ lnkv_g,
                          const float* __restrict__ lnkv_b,
                          const float* __restrict__ in_b) {
    __shared__ float kvn[256];
    __shared__ float rs[8], rss[8];
    __shared__ float s_mu, s_rstd;
    int row = blockIdx.x;        // b*64 + m
    int b = row >> 6, m = row & 63;
    int t = threadIdx.x, lane = t & 31, w = t >> 5;

    float v = z_multi[row*256 + t];
    float s = v, ss = v*v;
    #pragma unroll
    for (int o = 16; o; o >>= 1) {
        s  += __shfl_xor_sync(0xffffffffu, s,  o);
        ss += __shfl_xor_sync(0xffffffffu, ss, o);
    }
    if (lane == 0) { rs[w] = s; rss[w] = ss; }
    __syncthreads();
    if (t == 0) {
        float S = 0.f, SS = 0.f;
        for (int i = 0; i < 8; ++i) { S += rs[i]; SS += rss[i]; }
        float mu = S * (1.f/256.f);
        float var = SS * (1.f/256.f) - mu*mu;
        s_mu = mu; s_rstd = rsqrtf(var + 1e-5f);
    }
    __syncthreads();
    kvn[t] = (v - s_mu) * s_rstd * lnkv_g[t] + lnkv_b[t];
    __syncthreads();

    float aK = in_b[256 + t], aV = in_b[512 + t];
    #pragma unroll 4
    for (int d = 0; d < 256; ++d) {
        float x = kvn[d];
        aK += x * g_WkT[d*256 + t];
        aV += x * g_WvT[d*256 + t];
    }
    g_Kt[((b*8 + (t >> 5))*32 + (t & 31))*M_KV + m] = aK;
    g_V[row*256 + t] = aV;
}

// ---------------- fused per-point pipeline ----------------
__device__ __forceinline__ void matvec_acc(const float* __restrict__ W,
                                           const float* __restrict__ sIn,
                                           int t, float* acc) {
    #pragma unroll 4
    for (int d = 0; d < 256; ++d) {
        float wv = __ldg(W + d*256 + t);
        const float4* col = reinterpret_cast<const float4*>(sIn + d*PP);
        #pragma unroll
        for (int q = 0; q < P/4; ++q) {
            float4 x = col[q];
            acc[4*q+0] += x.x * wv;
            acc[4*q+1] += x.y * wv;
            acc[4*q+2] += x.z * wv;
            acc[4*q+3] += x.w * wv;
        }
    }
}

__device__ __forceinline__ void store_row(float* sOut, int t, const float* acc) {
    float4* row = reinterpret_cast<float4*>(sOut + t*PP);
    #pragma unroll
    for (int q = 0; q < P/4; ++q)
        row[q] = make_float4(acc[4*q], acc[4*q+1], acc[4*q+2], acc[4*q+3]);
}

__device__ __forceinline__ void apply_basis(int i, int t, float* acc,
        const float* sX0, const float* sR2,
        const float* __restrict__ gW, const float* __restrict__ gb,
        const float* __restrict__ gmu, const float* __restrict__ gga) {
    int idx = i*256 + t;
    float wx = gW[2*idx], wy = gW[2*idx+1];
    float bb = gb[idx];
    float mx = gmu[2*idx], my = gmu[2*idx+1];
    float ga = gga[idx];
    float mu2 = mx*mx + my*my;
    #pragma unroll
    for (int p = 0; p < P; ++p) {
        float x = sX0[2*p], y = sX0[2*p+1];
        float D = sR2[p] + mu2 - 2.f*(x*mx + y*my);
        float g = sinf(wx*x + wy*y + bb) * __expf(-0.5f * D * ga);
        acc[p] *= g;
    }
}

#define SMEM_FLOATS (3*256*PP + P*512 + P*36 + 2*P + P + P + P + 32)

__global__ void __launch_bounds__(256, 2)
main_kernel(const float* __restrict__ coords,
            const float* __restrict__ qp_W1, const float* __restrict__ qp_b1,
            const float* __restrict__ qp_b2,
            const float* __restrict__ lnq_g, const float* __restrict__ lnq_b,
            const float* __restrict__ in_b,  const float* __restrict__ out_b,
            const float* __restrict__ net1_b,
            const float* __restrict__ gabor_W, const float* __restrict__ gabor_b,
            const float* __restrict__ gabor_mu, const float* __restrict__ gabor_ga,
            const float* __restrict__ fin_W, const float* __restrict__ fin_b,
            float* __restrict__ out) {
    extern __shared__ float sm[];
    float* sA   = sm;                    // 256*PP
    float* sB   = sA + 256*PP;
    float* sZ   = sB + 256*PP;
    float* sS   = sZ + 256*PP;           // P*512 attention scores
    float* sF   = sS + P*512;            // P*36 final coeffs
    float* sX0  = sF + P*36;             // 2*P
    float* sR2  = sX0 + 2*P;             // P
    float* sMu  = sR2 + P;               // P
    float* sRstd= sMu + P;               // P
    float* sTab = sRstd + P;             // 32: cos/sin table

    int t = threadIdx.x;
    int lane = t & 31, w = t >> 5;
    int bid = blockIdx.x;
    int b  = bid >> 10;                  // NPTS/P = 1024
    int n0 = (bid & 1023) * P;

    if (t < 16) {
        float x = coords[(b*NPTS + n0 + t)*2 + 0];
        float y = coords[(b*NPTS + n0 + t)*2 + 1];
        sX0[2*t] = x; sX0[2*t+1] = y; sR2[t] = x*x + y*y;
        float sv, cv;
        sincosf(0.39269908169872414f * (float)t, &sv, &cv);  // pi/8 * t
        sTab[2*t] = cv; sTab[2*t+1] = sv;
    }
    __syncthreads();

    float acc[P];

    // ---- stage 1: q1 = GELU(x0 @ qp_W1^T + b1) ----
    {
        float wx = qp_W1[2*t], wy = qp_W1[2*t+1], bb = qp_b1[t];
        #pragma unroll
        for (int p = 0; p < P; ++p) {
            float u = wx*sX0[2*p] + wy*sX0[2*p+1] + bb;
            acc[p] = 0.5f * u * (1.f + erff(u * 0.70710678118654752f));
        }
        store_row(sA, t, acc);
    }
    __syncthreads();

    // ---- stage 2: q = q1 @ qp_W2^T + b2 ----
    #pragma unroll
    for (int p = 0; p < P; ++p) acc[p] = 0.f;
    matvec_acc(g_qpW2T, sA, t, acc);
    {
        float bb = qp_b2[t];
        #pragma unroll
        for (int p = 0; p < P; ++p) acc[p] += bb;
        store_row(sB, t, acc);
    }
    __syncthreads();

    // ---- LayerNorm(q): warp w handles points 2w, 2w+1 ----
    #pragma unroll
    for (int sub = 0; sub < 2; ++sub) {
        int p = w*2 + sub;
        float s = 0.f, ss = 0.f;
        #pragma unroll
        for (int j = 0; j < 8; ++j) {
            float v = sB[(lane + 32*j)*PP + p];
            s += v; ss += v*v;
        }
        #pragma unroll
        for (int o = 16; o; o >>= 1) {
            s  += __shfl_xor_sync(0xffffffffu, s,  o);
            ss += __shfl_xor_sync(0xffffffffu, ss, o);
        }
        if (lane == 0) {
            float mu = s * (1.f/256.f);
            float var = ss * (1.f/256.f) - mu*mu;
            sMu[p] = mu; sRstd[p] = rsqrtf(var + 1e-5f);
        }
    }
    __syncthreads();
    {
        float g = lnq_g[t], be = lnq_b[t];
        float* row = &sB[t*PP];
        #pragma unroll
        for (int p = 0; p < P; ++p)
            row[p] = (row[p] - sMu[p]) * sRstd[p] * g + be;
    }
    __syncthreads();

    // ---- Q projection (scaled by 1/sqrt(32)) ----
    #pragma unroll
    for (int p = 0; p < P; ++p) acc[p] = 0.f;
    matvec_acc(g_WqT, sB, t, acc);
    {
        float bb = in_b[t];
        const float sc = 0.17677669529663687f;
        #pragma unroll
        for (int p = 0; p < P; ++p) acc[p] = (acc[p] + bb) * sc;
        store_row(sA, t, acc);
    }
    __syncthreads();

    // ---- attention scores: 512 (head,m) pairs, 2 per thread ----
    for (int rep = 0; rep < 2; ++rep) {
        int pair = t + rep*256;
        int hh = pair >> 6, m = pair & 63;
        const float* Kp = &g_Kt[((b*8 + hh)*32)*M_KV + m];
        float a[P];
        #pragma unroll
        for (int p = 0; p < P; ++p) a[p] = 0.f;
        #pragma unroll 4
        for (int k = 0; k < 32; ++k) {
            float kv = Kp[k*M_KV];
            const float4* col = reinterpret_cast<const float4*>(sA + (hh*32 + k)*PP);
            #pragma unroll
            for (int q = 0; q < P/4; ++q) {
                float4 x = col[q];
                a[4*q+0] += x.x * kv;
                a[4*q+1] += x.y * kv;
                a[4*q+2] += x.z * kv;
                a[4*q+3] += x.w * kv;
            }
        }
        #pragma unroll
        for (int p = 0; p < P; ++p) sS[p*512 + pair] = a[p];
    }
    __syncthreads();

    // ---- softmax over m (rows = P*8 = 128) ----
    for (int rr = 0; rr < 16; ++rr) {
        int r = w + rr*8;
        int p = r >> 3, hh = r & 7;
        float* base = &sS[p*512 + hh*64];
        float v0 = base[lane], v1 = base[lane+32];
        float mx = fmaxf(v0, v1);
        #pragma unroll
        for (int o = 16; o; o >>= 1) mx = fmaxf(mx, __shfl_xor_sync(0xffffffffu, mx, o));
        float e0 = __expf(v0 - mx), e1 = __expf(v1 - mx);
        float sum = e0 + e1;
        #pragma unroll
        for (int o = 16; o; o >>= 1) sum += __shfl_xor_sync(0xffffffffu, sum, o);
        float inv = 1.f / sum;
        base[lane] = e0*inv; base[lane+32] = e1*inv;
    }
    __syncthreads();

    // ---- ctx = attn @ V ----
    #pragma unroll
    for (int p = 0; p < P; ++p) acc[p] = 0.f;
    {
        int hh = t >> 5;
        #pragma unroll 2
        for (int m = 0; m < M_KV; ++m) {
            float vv = g_V[(b*M_KV + m)*256 + t];
            #pragma unroll
            for (int p = 0; p < P; ++p) acc[p] += sS[p*512 + hh*64 + m] * vv;
        }
        store_row(sB, t, acc);
    }
    __syncthreads();

    // ---- z = ctx @ out_W^T + out_b ----
    #pragma unroll
    for (int p = 0; p < P; ++p) acc[p] = 0.f;
    matvec_acc(g_outWT, sB, t, acc);
    {
        float bb = out_b[t];
        #pragma unroll
        for (int p = 0; p < P; ++p) acc[p] += bb;
        store_row(sZ, t, acc);
    }
    __syncthreads();

    // ---- MFN layer 0 ----
    #pragma unroll
    for (int p = 0; p < P; ++p) acc[p] = 0.f;
    matvec_acc(g_net2T, sZ, t, acc);
    apply_basis(0, t, acc, sX0, sR2, gabor_W, gabor_b, gabor_mu, gabor_ga);
    store_row(sA, t, acc);
    __syncthreads();

    // ---- MFN layers 1..4 ----
    float* cur = sA; float* nxt = sB;
    for (int i = 1; i <= 4; ++i) {
        #pragma unroll
        for (int p = 0; p < P; ++p) acc[p] = 0.f;
        matvec_acc(g_net1T + (i-1)*65536, cur, t, acc);
        matvec_acc(g_net2T + i*65536, sZ, t, acc);
        float bb = net1_b[(i-1)*256 + t];
        #pragma unroll
        for (int p = 0; p < P; ++p) acc[p] += bb;
        apply_basis(i, t, acc, sX0, sR2, gabor_W, gabor_b, gabor_mu, gabor_ga);
        store_row(nxt, t, acc);
        __syncthreads();
        float* tmp = cur; cur = nxt; nxt = tmp;
    }
    // final x is in `cur`

    // ---- fin: out[o] = x @ fin_W[o] + fin_b[o], o<36 (4 threads per o) ----
    {
        int g = t >> 2, j = t & 3;
        float part[P];
        #pragma unroll
        for (int p = 0; p < P; ++p) part[p] = 0.f;
        if (g < 36) {
            const float* Wo = &fin_W[g*256];
            for (int k = 0; k < 64; ++k) {
                int h = (k << 2) + j;
                float wv = Wo[h];
                const float* col = &cur[h*PP];
                #pragma unroll
                for (int p = 0; p < P; ++p) part[p] += col[p] * wv;
            }
        }
        #pragma unroll
        for (int p = 0; p < P; ++p) {
            part[p] += __shfl_xor_sync(0xffffffffu, part[p], 1);
            part[p] += __shfl_xor_sync(0xffffffffu, part[p], 2);
        }
        if (g < 36 && j == 0) {
            float bb = fin_b[g];
            #pragma unroll
            for (int p = 0; p < P; ++p) sF[p*36 + g] = part[p] + bb;
        }
    }
    __syncthreads();

    // ---- irfft (n=16, ortho) + write output [B,16,N,2] ----
    {
        int inner = t & 31;
        int p = inner >> 1, c = inner & 1;
        const float* Fp = &sF[p*36];
        #pragma unroll
        for (int it = 0; it < 2; ++it) {
            int tt = (t >> 5) + 8*it;
            float a = Fp[c*2];                       // f=0 real
            float f8 = Fp[8*4 + c*2];                // f=8 real
            a += (tt & 1) ? -f8 : f8;
            #pragma unroll
            for (int f = 1; f < 8; ++f) {
                float re = Fp[f*4 + c*2];
                float im = Fp[f*4 + c*2 + 1];
                int k = (f*tt) & 15;
                a += 2.f * (re * sTab[2*k] - im * sTab[2*k+1]);
            }
            out[(((b*16 + tt)*NPTS) + n0 + p)*2 + c] = 0.25f * a;
        }
    }
}

// ---------------- launch ----------------
extern "C" void kernel_launch(void* const* d_in, const int* in_sizes, int n_in,
                              void* d_out, int out_size) {
    const float* z_multi = (const float*)d_in[0];
    const float* coords  = (const float*)d_in[1];
    const float* gabor_W = (const float*)d_in[2];
    const float* gabor_b = (const float*)d_in[3];
    const float* gabor_mu= (const float*)d_in[4];
    const float* gabor_ga= (const float*)d_in[5];
    const float* net1_W  = (const float*)d_in[6];
    const float* net1_b  = (const float*)d_in[7];
    const float* net2_W  = (const float*)d_in[8];
    const float* qp_W1   = (const float*)d_in[9];
    const float* qp_b1   = (const float*)d_in[10];
    const float* qp_W2   = (const float*)d_in[11];
    const float* qp_b2   = (const float*)d_in[12];
    const float* in_W    = (const float*)d_in[13];
    const float* in_b    = (const float*)d_in[14];
    const float* out_W   = (const float*)d_in[15];
    const float* out_b   = (const float*)d_in[16];
    const float* lnq_g   = (const float*)d_in[17];
    const float* lnq_b   = (const float*)d_in[18];
    const float* lnkv_g  = (const float*)d_in[19];
    const float* lnkv_b  = (const float*)d_in[20];
    const float* fin_W   = (const float*)d_in[21];
    const float* fin_b   = (const float*)d_in[22];
    float* out = (float*)d_out;

    size_t smem = SMEM_FLOATS * sizeof(float);
    cudaFuncSetAttribute(main_kernel, cudaFuncAttributeMaxDynamicSharedMemorySize, (int)smem);

    prep_transpose<<<dim3(256, 14), 256>>>(qp_W2, in_W, out_W, net2_W, net1_W);
    kv_kernel<<<BATCH*M_KV, 256>>>(z_multi, lnkv_g, lnkv_b, in_b);
    main_kernel<<<BATCH*(NPTS/P), 256, smem>>>(coords, qp_W1, qp_b1, qp_b2,
                                               lnq_g, lnq_b, in_b, out_b, net1_b,
                                               gabor_W, gabor_b, gabor_mu, gabor_ga,
                                               fin_W, fin_b, out);
}

// round 2
// speedup vs baseline: 1.0988x; 1.0988x over previous
#include <cuda_runtime.h>
#include <math.h>

#define BATCH 8
#define NPTS  16384
#define M_KV  64
#define P     16
#define PP    20   // pitch for [d][p] staging layout (floats)

typedef unsigned long long ull;

// ---------------- packed f32x2 helpers ----------------
__device__ __forceinline__ void fma2(ull& a, ull x, ull w) {
    asm("fma.rn.f32x2 %0, %1, %2, %0;" : "+l"(a) : "l"(x), "l"(w));
}
__device__ __forceinline__ float fold2(ull v) {
    float lo, hi;
    asm("mov.b64 {%0,%1}, %2;" : "=f"(lo), "=f"(hi) : "l"(v));
    return lo + hi;
}
__device__ __forceinline__ void unpack2(ull v, float& lo, float& hi) {
    asm("mov.b64 {%0,%1}, %2;" : "=f"(lo), "=f"(hi) : "l"(v));
}
__device__ __forceinline__ ull pack2(float lo, float hi) {
    ull r; asm("mov.b64 %0, {%1,%2};" : "=l"(r) : "f"(lo), "f"(hi)); return r;
}

// ---------------- scratch ----------------
// all 256x256 weights packed as quads: W4[(d/4)*1024 + t*4 + (d&3)] = W_src[t][d]
__device__ float g_qpW2T[65536];
__device__ float g_WqT  [65536];
__device__ float g_WkT  [65536];
__device__ float g_WvT  [65536];
__device__ float g_outWT[65536];
__device__ float g_net2T[5*65536];
__device__ float g_net1T[4*65536];
__device__ float g_Kt   [BATCH*8*32*M_KV];      // [b][head][k][m]
__device__ float g_Vt   [BATCH*32*256*2];       // [b][m/2][t][2] = V[m][t] pairs

// ---------------- prep: pack all 256x256 weights into quad layout ----------------
__global__ void prep_pack(const float* __restrict__ qp_W2,
                          const float* __restrict__ in_W,
                          const float* __restrict__ out_W,
                          const float* __restrict__ net2_W,
                          const float* __restrict__ net1_W) {
    int mid = blockIdx.y;
    int quad = blockIdx.x;     // 0..63
    int t = threadIdx.x;       // 0..255
    const float* src;
    float* dst;
    switch (mid) {
        case 0: src = qp_W2;            dst = g_qpW2T; break;
        case 1: src = in_W;             dst = g_WqT;   break;
        case 2: src = in_W + 65536;     dst = g_WkT;   break;
        case 3: src = in_W + 131072;    dst = g_WvT;   break;
        case 4: src = out_W;            dst = g_outWT; break;
        default:
            if (mid < 10) { src = net2_W + (mid-5)*65536;  dst = g_net2T + (mid-5)*65536; }
            else          { src = net1_W + (mid-10)*65536; dst = g_net1T + (mid-10)*65536; }
    }
    float4 v = *reinterpret_cast<const float4*>(src + t*256 + quad*4);
    *reinterpret_cast<float4*>(dst + quad*1024 + t*4) = v;
}

// ---------------- prep: LayerNorm(z) -> K, V ----------------
__global__ void kv_kernel(const float* __restrict__ z_multi,
                          const float* __restrict__ lnkv_g,
                          const float* __restrict__ lnkv_b,
                          const float* __restrict__ in_b) {
    __shared__ float kvn[256];
    __shared__ float rs[8], rss[8];
    __shared__ float s_mu, s_rstd;
    int row = blockIdx.x;        // b*64 + m
    int b = row >> 6, m = row & 63;
    int t = threadIdx.x, lane = t & 31, w = t >> 5;

    float v = z_multi[row*256 + t];
    float s = v, ss = v*v;
    #pragma unroll
    for (int o = 16; o; o >>= 1) {
        s  += __shfl_xor_sync(0xffffffffu, s,  o);
        ss += __shfl_xor_sync(0xffffffffu, ss, o);
    }
    if (lane == 0) { rs[w] = s; rss[w] = ss; }
    __syncthreads();
    if (t == 0) {
        float S = 0.f, SS = 0.f;
        for (int i = 0; i < 8; ++i) { S += rs[i]; SS += rss[i]; }
        float mu = S * (1.f/256.f);
        float var = SS * (1.f/256.f) - mu*mu;
        s_mu = mu; s_rstd = rsqrtf(var + 1e-5f);
    }
    __syncthreads();
    kvn[t] = (v - s_mu) * s_rstd * lnkv_g[t] + lnkv_b[t];
    __syncthreads();

    float aK = in_b[256 + t], aV = in_b[512 + t];
    #pragma unroll 4
    for (int quad = 0; quad < 64; ++quad) {
        float4 x  = *reinterpret_cast<const float4*>(kvn + quad*4);
        float4 wK = *reinterpret_cast<const float4*>(g_WkT + quad*1024 + t*4);
        float4 wV = *reinterpret_cast<const float4*>(g_WvT + quad*1024 + t*4);
        aK += x.x*wK.x + x.y*wK.y + x.z*wK.z + x.w*wK.w;
        aV += x.x*wV.x + x.y*wV.y + x.z*wV.z + x.w*wV.w;
    }
    g_Kt[((b*8 + (t >> 5))*32 + (t & 31))*M_KV + m] = aK;
    g_Vt[((b*32 + (m >> 1))*256 + t)*2 + (m & 1)] = aV;
}

// ---------------- packed matvec: acc2[p] += W[t][:] dot x[p][:] (d-paired) ----------------
__device__ __forceinline__ void matvec2_acc(const float* __restrict__ W4,
                                            const float* __restrict__ sIn,  // [p][256]
                                            int t, ull* acc) {
    const ulonglong2* wp = reinterpret_cast<const ulonglong2*>(W4 + t*4);
    ulonglong2 w = wp[0];
    #pragma unroll 2
    for (int quad = 0; quad < 64; ++quad) {
        ulonglong2 wn = w;
        if (quad < 63) wn = wp[(quad+1)*256];
        const float* base = sIn + quad*4;
        #pragma unroll
        for (int p = 0; p < P; ++p) {
            ulonglong2 x = *reinterpret_cast<const ulonglong2*>(base + p*256);
            fma2(acc[p], x.x, w.x);
            fma2(acc[p], x.y, w.y);
        }
        w = wn;
    }
}

__device__ __forceinline__ void apply_basis(int i, int t, float* f,
        const float* sX0, const float* sR2,
        const float* __restrict__ gW, const float* __restrict__ gb,
        const float* __restrict__ gmu, const float* __restrict__ gga) {
    int idx = i*256 + t;
    float wx = gW[2*idx], wy = gW[2*idx+1];
    float bb = gb[idx];
    float mx = gmu[2*idx], my = gmu[2*idx+1];
    float ga = gga[idx];
    float mu2 = mx*mx + my*my;
    #pragma unroll
    for (int p = 0; p < P; ++p) {
        float x = sX0[2*p], y = sX0[2*p+1];
        float D = sR2[p] + mu2 - 2.f*(x*mx + y*my);
        float g = sinf(wx*x + wy*y + bb) * __expf(-0.5f * D * ga);
        f[p] *= g;
    }
}

// sA, sB need max(16*256, 256*PP)=5120; sZ 4096; sS P*512; sF P*36
#define SMEM_FLOATS (5120 + 5120 + 4096 + P*512 + P*36 + 2*P + P + P + P + 32)

__global__ void __launch_bounds__(256, 2)
main_kernel(const float* __restrict__ coords,
            const float* __restrict__ qp_W1, const float* __restrict__ qp_b1,
            const float* __restrict__ qp_b2,
            const float* __restrict__ lnq_g, const float* __restrict__ lnq_b,
            const float* __restrict__ in_b,  const float* __restrict__ out_b,
            const float* __restrict__ net1_b,
            const float* __restrict__ gabor_W, const float* __restrict__ gabor_b,
            const float* __restrict__ gabor_mu, const float* __restrict__ gabor_ga,
            const float* __restrict__ fin_W, const float* __restrict__ fin_b,
            float* __restrict__ out) {
    extern __shared__ float sm[];
    float* sA   = sm;                    // 5120
    float* sB   = sA + 5120;             // 5120
    float* sZ   = sB + 5120;             // 4096 ([p][256])
    float* sS   = sZ + 4096;             // P*512 attention scores
    float* sF   = sS + P*512;            // P*36
    float* sX0  = sF + P*36;             // 2P
    float* sR2  = sX0 + 2*P;
    float* sMu  = sR2 + P;
    float* sRstd= sMu + P;
    float* sTab = sRstd + P;             // 32

    int t = threadIdx.x;
    int lane = t & 31, w = t >> 5;
    int bid = blockIdx.x;
    int b  = bid >> 10;                  // NPTS/P = 1024
    int n0 = (bid & 1023) * P;

    if (t < 16) {
        float x = coords[(b*NPTS + n0 + t)*2 + 0];
        float y = coords[(b*NPTS + n0 + t)*2 + 1];
        sX0[2*t] = x; sX0[2*t+1] = y; sR2[t] = x*x + y*y;
        float sv, cv;
        sincosf(0.39269908169872414f * (float)t, &sv, &cv);  // pi/8 * t
        sTab[2*t] = cv; sTab[2*t+1] = sv;
    }
    __syncthreads();

    ull acc[P];
    float f[P];

    // ---- stage 1: q1 = GELU(x0 @ qp_W1^T + b1), store [p][256] in sA ----
    {
        float wx = qp_W1[2*t], wy = qp_W1[2*t+1], bb = qp_b1[t];
        #pragma unroll
        for (int p = 0; p < P; ++p) {
            float u = wx*sX0[2*p] + wy*sX0[2*p+1] + bb;
            sA[p*256 + t] = 0.5f * u * (1.f + erff(u * 0.70710678118654752f));
        }
    }
    __syncthreads();

    // ---- stage 2: q = q1 @ qp_W2^T + b2 ----
    #pragma unroll
    for (int p = 0; p < P; ++p) acc[p] = 0ull;
    matvec2_acc(g_qpW2T, sA, t, acc);
    {
        float bb = qp_b2[t];
        #pragma unroll
        for (int p = 0; p < P; ++p) { f[p] = fold2(acc[p]) + bb; sB[p*256 + t] = f[p]; }
    }
    __syncthreads();

    // ---- LayerNorm(q) stats: warp w handles points 2w, 2w+1 ----
    #pragma unroll
    for (int sub = 0; sub < 2; ++sub) {
        int p = w*2 + sub;
        const float4* row = reinterpret_cast<const float4*>(sB + p*256);
        float s = 0.f, ss = 0.f;
        #pragma unroll
        for (int j = 0; j < 2; ++j) {
            float4 v = row[lane + 32*j];
            s  += v.x + v.y + v.z + v.w;
            ss += v.x*v.x + v.y*v.y + v.z*v.z + v.w*v.w;
        }
        #pragma unroll
        for (int o = 16; o; o >>= 1) {
            s  += __shfl_xor_sync(0xffffffffu, s,  o);
            ss += __shfl_xor_sync(0xffffffffu, ss, o);
        }
        if (lane == 0) {
            float mu = s * (1.f/256.f);
            float var = ss * (1.f/256.f) - mu*mu;
            sMu[p] = mu; sRstd[p] = rsqrtf(var + 1e-5f);
        }
    }
    __syncthreads();
    {
        float g = lnq_g[t], be = lnq_b[t];
        #pragma unroll
        for (int p = 0; p < P; ++p)
            sB[p*256 + t] = (f[p] - sMu[p]) * sRstd[p] * g + be;
    }
    __syncthreads();

    // ---- Q projection (scaled), stage into sA as [d][p] pitch PP ----
    #pragma unroll
    for (int p = 0; p < P; ++p) acc[p] = 0ull;
    matvec2_acc(g_WqT, sB, t, acc);
    {
        float bb = in_b[t];
        const float sc = 0.17677669529663687f;   // 1/sqrt(32)
        #pragma unroll
        for (int p = 0; p < P; ++p) f[p] = (fold2(acc[p]) + bb) * sc;
        float4* row = reinterpret_cast<float4*>(sA + t*PP);
        #pragma unroll
        for (int q = 0; q < 4; ++q)
            row[q] = make_float4(f[4*q], f[4*q+1], f[4*q+2], f[4*q+3]);
    }
    __syncthreads();

    // ---- attention scores: 512 (head,m) pairs, 2 per thread ----
    #pragma unroll
    for (int rep = 0; rep < 2; ++rep) {
        int pair = t + rep*256;
        int hh = pair >> 6, m = pair & 63;
        const float* Kp = &g_Kt[((b*8 + hh)*32)*M_KV + m];
        ull a2[8];
        #pragma unroll
        for (int j = 0; j < 8; ++j) a2[j] = 0ull;
        #pragma unroll 4
        for (int k = 0; k < 32; ++k) {
            float kv = Kp[k*M_KV];
            ull kk = pack2(kv, kv);
            const ulonglong2* col = reinterpret_cast<const ulonglong2*>(sA + (hh*32 + k)*PP);
            #pragma unroll
            for (int q = 0; q < 4; ++q) {
                ulonglong2 x = col[q];
                fma2(a2[2*q],   x.x, kk);
                fma2(a2[2*q+1], x.y, kk);
            }
        }
        #pragma unroll
        for (int j = 0; j < 8; ++j) {
            float lo, hi; unpack2(a2[j], lo, hi);
            sS[(2*j)*512 + pair] = lo;
            sS[(2*j+1)*512 + pair] = hi;
        }
    }
    __syncthreads();

    // ---- softmax over m ----
    for (int rr = 0; rr < 16; ++rr) {
        int r = w + rr*8;
        int p = r >> 3, hh = r & 7;
        float* base = &sS[p*512 + hh*64];
        float v0 = base[lane], v1 = base[lane+32];
        float mx = fmaxf(v0, v1);
        #pragma unroll
        for (int o = 16; o; o >>= 1) mx = fmaxf(mx, __shfl_xor_sync(0xffffffffu, mx, o));
        float e0 = __expf(v0 - mx), e1 = __expf(v1 - mx);
        float sum = e0 + e1;
        #pragma unroll
        for (int o = 16; o; o >>= 1) sum += __shfl_xor_sync(0xffffffffu, sum, o);
        float inv = 1.f / sum;
        base[lane] = e0*inv; base[lane+32] = e1*inv;
    }
    __syncthreads();

    // ---- ctx = attn @ V (m-paired), store [p][256] in sB ----
    {
        int hh = t >> 5;
        #pragma unroll
        for (int p = 0; p < P; ++p) acc[p] = 0ull;
        const float* Vb = g_Vt + b*32*512;
        #pragma unroll 2
        for (int m = 0; m < M_KV; m += 2) {
            ull vv = *reinterpret_cast<const ull*>(Vb + ((m>>1)*256 + t)*2);
            #pragma unroll
            for (int p = 0; p < P; ++p) {
                ull ap = *reinterpret_cast<const ull*>(&sS[p*512 + hh*64 + m]);
                fma2(acc[p], ap, vv);
            }
        }
        #pragma unroll
        for (int p = 0; p < P; ++p) sB[p*256 + t] = fold2(acc[p]);
    }
    __syncthreads();

    // ---- z = ctx @ out_W^T + out_b, store [p][256] in sZ ----
    #pragma unroll
    for (int p = 0; p < P; ++p) acc[p] = 0ull;
    matvec2_acc(g_outWT, sB, t, acc);
    {
        float bb = out_b[t];
        #pragma unroll
        for (int p = 0; p < P; ++p) sZ[p*256 + t] = fold2(acc[p]) + bb;
    }
    __syncthreads();

    // ---- MFN layer 0 ----
    #pragma unroll
    for (int p = 0; p < P; ++p) acc[p] = 0ull;
    matvec2_acc(g_net2T, sZ, t, acc);
    #pragma unroll
    for (int p = 0; p < P; ++p) f[p] = fold2(acc[p]);
    apply_basis(0, t, f, sX0, sR2, gabor_W, gabor_b, gabor_mu, gabor_ga);
    #pragma unroll
    for (int p = 0; p < P; ++p) sA[p*256 + t] = f[p];
    __syncthreads();

    // ---- MFN layers 1..4 ----
    float* cur = sA; float* nxt = sB;
    for (int i = 1; i <= 4; ++i) {
        #pragma unroll
        for (int p = 0; p < P; ++p) acc[p] = 0ull;
        matvec2_acc(g_net1T + (i-1)*65536, cur, t, acc);
        matvec2_acc(g_net2T + i*65536, sZ, t, acc);
        float bb = net1_b[(i-1)*256 + t];
        #pragma unroll
        for (int p = 0; p < P; ++p) f[p] = fold2(acc[p]) + bb;
        apply_basis(i, t, f, sX0, sR2, gabor_W, gabor_b, gabor_mu, gabor_ga);
        if (i < 4) {
            #pragma unroll
            for (int p = 0; p < P; ++p) nxt[p*256 + t] = f[p];
        } else {
            // final layer: store [d][p] pitch PP into sA for fin
            float4* row = reinterpret_cast<float4*>(sA + t*PP);
            #pragma unroll
            for (int q = 0; q < 4; ++q)
                row[q] = make_float4(f[4*q], f[4*q+1], f[4*q+2], f[4*q+3]);
        }
        __syncthreads();
        float* tmp = cur; cur = nxt; nxt = tmp;
    }
    // final x is in sA, [d][p] pitch PP layout

    // ---- fin: out[o] = x @ fin_W[o] + fin_b[o], o<36 (4 threads per o) ----
    {
        int g = t >> 2, j = t & 3;
        ull part2[8];
        #pragma unroll
        for (int q = 0; q < 8; ++q) part2[q] = 0ull;
        if (g < 36) {
            const float* Wo = &fin_W[g*256];
            #pragma unroll 4
            for (int k = 0; k < 64; ++k) {
                int h = (k << 2) + j;
                float wv = Wo[h];
                ull ww = pack2(wv, wv);
                const ulonglong2* col = reinterpret_cast<const ulonglong2*>(sA + h*PP);
                #pragma unroll
                for (int q = 0; q < 4; ++q) {
                    ulonglong2 x = col[q];
                    fma2(part2[2*q],   x.x, ww);
                    fma2(part2[2*q+1], x.y, ww);
                }
            }
        }
        float part[P];
        #pragma unroll
        for (int q = 0; q < 8; ++q) unpack2(part2[q], part[2*q], part[2*q+1]);
        #pragma unroll
        for (int p = 0; p < P; ++p) {
            part[p] += __shfl_xor_sync(0xffffffffu, part[p], 1);
            part[p] += __shfl_xor_sync(0xffffffffu, part[p], 2);
        }
        if (g < 36 && j == 0) {
            float bb = fin_b[g];
            #pragma unroll
            for (int p = 0; p < P; ++p) sF[p*36 + g] = part[p] + bb;
        }
    }
    __syncthreads();

    // ---- irfft (n=16, ortho) + write output [B,16,N,2] ----
    {
        int inner = t & 31;
        int p = inner >> 1, c = inner & 1;
        const float* Fp = &sF[p*36];
        #pragma unroll
        for (int it = 0; it < 2; ++it) {
            int tt = (t >> 5) + 8*it;
            float a = Fp[c*2];                       // f=0 real
            float f8 = Fp[8*4 + c*2];                // f=8 real
            a += (tt & 1) ? -f8 : f8;
            #pragma unroll
            for (int fq = 1; fq < 8; ++fq) {
                float re = Fp[fq*4 + c*2];
                float im = Fp[fq*4 + c*2 + 1];
                int k = (fq*tt) & 15;
                a += 2.f * (re * sTab[2*k] - im * sTab[2*k+1]);
            }
            out[(((b*16 + tt)*NPTS) + n0 + p)*2 + c] = 0.25f * a;
        }
    }
}

// ---------------- launch ----------------
extern "C" void kernel_launch(void* const* d_in, const int* in_sizes, int n_in,
                              void* d_out, int out_size) {
    const float* z_multi = (const float*)d_in[0];
    const float* coords  = (const float*)d_in[1];
    const float* gabor_W = (const float*)d_in[2];
    const float* gabor_b = (const float*)d_in[3];
    const float* gabor_mu= (const float*)d_in[4];
    const float* gabor_ga= (const float*)d_in[5];
    const float* net1_W  = (const float*)d_in[6];
    const float* net1_b  = (const float*)d_in[7];
    const float* net2_W  = (const float*)d_in[8];
    const float* qp_W1   = (const float*)d_in[9];
    const float* qp_b1   = (const float*)d_in[10];
    const float* qp_W2   = (const float*)d_in[11];
    const float* qp_b2   = (const float*)d_in[12];
    const float* in_W    = (const float*)d_in[13];
    const float* in_b    = (const float*)d_in[14];
    const float* out_W   = (const float*)d_in[15];
    const float* out_b   = (const float*)d_in[16];
    const float* lnq_g   = (const float*)d_in[17];
    const float* lnq_b   = (const float*)d_in[18];
    const float* lnkv_g  = (const float*)d_in[19];
    const float* lnkv_b  = (const float*)d_in[20];
    const float* fin_W   = (const float*)d_in[21];
    const float* fin_b   = (const float*)d_in[22];
    float* out = (float*)d_out;

    size_t smem = SMEM_FLOATS * sizeof(float);
    cudaFuncSetAttribute(main_kernel, cudaFuncAttributeMaxDynamicSharedMemorySize, (int)smem);

    prep_pack<<<dim3(64, 14), 256>>>(qp_W2, in_W, out_W, net2_W, net1_W);
    kv_kernel<<<BATCH*M_KV, 256>>>(z_multi, lnkv_g, lnkv_b, in_b);
    main_kernel<<<BATCH*(NPTS/P), 256, smem>>>(coords, qp_W1, qp_b1, qp_b2,
                                               lnq_g, lnq_b, in_b, out_b, net1_b,
                                               gabor_W, gabor_b, gabor_mu, gabor_ga,
                                               fin_W, fin_b, out);
}